// round 15
// baseline (speedup 1.0000x reference)
#include <cuda_runtime.h>
#include <cuda_bf16.h>
#include <cuda_fp16.h>
#include <cstdint>
#include <cstddef>

// ---------------------------------------------------------------------------
// BiAffine, sm_100 base target (no tcgen05 at this compile target).
//   dir1: Sh = S2@W1^T ; sc = S1@Sh^T ; P = softmax(sc) ; out1 = P@S2
//   dir2: Sh = S1@W2^T ; sc = S2@Sh^T ; P = softmax(sc) ; out2 = P@S1
// proj/scores: fp16 hi/lo 3-product mma.sync.
// PV: single-product fp16 mma.sync.
// R15: occupancy attack — CTA 128x64, warp 32x32, 2-stage 24KB pipeline,
// __launch_bounds__(256,3) -> 3 CTAs/SM = 24 warps (6/SMSP), was 16 (4/SMSP).
// ---------------------------------------------------------------------------

#define BATCH 8
#define SEQ   2048
#define HDIM  1024

#define E1 ((size_t)BATCH * SEQ * HDIM)   // 16777216
#define EW ((size_t)HDIM * HDIM)          // 1048576
#define ES ((size_t)BATCH * SEQ * SEQ)    // 33554432

// ---- static scratch (no allocations allowed) ------------------------------
__device__ __half g_s1h[E1], g_s1l[E1], g_s2h[E1], g_s2l[E1];
__device__ __half g_w1h[EW], g_w1l[EW], g_w2h[EW], g_w2l[EW];
__device__ __half g_shh[E1], g_shl[E1];
__device__ __half g_s1t[E1], g_s2t[E1];   // transposed S, fp16
__device__ float  g_sc[ES];
__device__ __half g_at[ES];               // softmax probs, fp16

// ---------------------------------------------------------------------------
// helpers
// ---------------------------------------------------------------------------
__device__ __forceinline__ void cp16(uint32_t s, const void* g) {
    asm volatile("cp.async.cg.shared.global [%0], [%1], 16;" :: "r"(s), "l"(g));
}
__device__ __forceinline__ void cp_commit() {
    asm volatile("cp.async.commit_group;");
}
__device__ __forceinline__ void cp_wait0() {
    asm volatile("cp.async.wait_group 0;");
}

__device__ __forceinline__ void ldmx4(uint32_t* r, uint32_t addr) {
    asm volatile("ldmatrix.sync.aligned.m8n8.x4.shared.b16 {%0,%1,%2,%3}, [%4];"
                 : "=r"(r[0]), "=r"(r[1]), "=r"(r[2]), "=r"(r[3]) : "r"(addr));
}

__device__ __forceinline__ void mma16816h(float* c, const uint32_t* a,
                                          uint32_t b0, uint32_t b1) {
    asm volatile(
        "mma.sync.aligned.m16n8k16.row.col.f32.f16.f16.f32 "
        "{%0,%1,%2,%3}, {%4,%5,%6,%7}, {%8,%9}, {%0,%1,%2,%3};"
        : "+f"(c[0]), "+f"(c[1]), "+f"(c[2]), "+f"(c[3])
        : "r"(a[0]), "r"(a[1]), "r"(a[2]), "r"(a[3]), "r"(b0), "r"(b1));
}

__device__ __forceinline__ void hsplit(float x, __half& h, __half& l) {
    h = __float2half_rn(x);
    l = __float2half_rn(x - __half2float(h));
}

// ---------------------------------------------------------------------------
// gemm3x: C = Ah@Bh^T + Ah@Bl^T + Al@Bh^T  (fp16 hi/lo)
// CTA 128x64, 8 warps (4m x 2n), warp 32x32, BK=32, 2-stage cp.async,
// 3 CTAs/SM. MODE 0: C0 = fp32. MODE 1: C0 = fp16 hi, C1 = fp16 lo.
// SMEM stage 24KB: A 128 rows x [hi 64B | lo 64B] (16KB), B 64 rows (8KB).
// ---------------------------------------------------------------------------
#define STAGE 24576
#define SMEM_REQ (2 * STAGE + 1024)

template <int MODE>
__global__ __launch_bounds__(256, 3) void gemm3x(
    const __half* __restrict__ Ah, const __half* __restrict__ Al,
    const __half* __restrict__ Bh, const __half* __restrict__ Bl,
    void* __restrict__ C0v, void* __restrict__ C1v,
    int M, int N, int K, size_t sAb, size_t sBb, size_t sCb)
{
    extern __shared__ char smem[];
    const int tid  = threadIdx.x;
    const int wid  = tid >> 5;
    const int lane = tid & 31;
    const int wm   = wid >> 1;      // 0..3 (m, 32 each)
    const int wn   = wid & 1;       // 0..1 (n, 32 each)
    const int m0   = blockIdx.y * 128;
    const int n0   = blockIdx.x * 64;
    const int b    = blockIdx.z;

    Ah += (size_t)b * sAb;  Al += (size_t)b * sAb;
    Bh += (size_t)b * sBb;  Bl += (size_t)b * sBb;

    uint32_t sbase = (uint32_t)__cvta_generic_to_shared(smem);
    const uint32_t ST0 = (sbase + 1023) & ~1023u;

    const int T = K >> 5;

    const int fc  = tid & 7;        // 16B chunk
    const int fr0 = tid >> 3;       // 0..31

    auto fill = [&](int kt, int s) {
        const uint32_t sa = ST0 + s * STAGE;
        const uint32_t sb = sa + 16384;
        const int kg = kt * 32 + (fc & 3) * 8;
#pragma unroll
        for (int i = 0; i < 4; i++) {           // A: 128 rows
            int row = fr0 + i * 32;
            uint32_t so = (uint32_t)row * 128 + (uint32_t)(fc ^ (row & 7)) * 16;
            const __half* ga = (fc < 4)
                ? Ah + (size_t)(m0 + row) * K + kg
                : Al + (size_t)(m0 + row) * K + kg;
            cp16(sa + so, ga);
        }
#pragma unroll
        for (int i = 0; i < 2; i++) {           // B: 64 rows
            int row = fr0 + i * 32;
            uint32_t so = (uint32_t)row * 128 + (uint32_t)(fc ^ (row & 7)) * 16;
            const __half* gb = (fc < 4)
                ? Bh + (size_t)(n0 + row) * K + kg
                : Bl + (size_t)(n0 + row) * K + kg;
            cp16(sb + so, gb);
        }
        cp_commit();
    };

    float acc[2][4][4];
#pragma unroll
    for (int mt = 0; mt < 2; mt++)
#pragma unroll
        for (int nt = 0; nt < 4; nt++)
#pragma unroll
            for (int j = 0; j < 4; j++) acc[mt][nt][j] = 0.0f;

    fill(0, 0);

    for (int kt = 0; kt < T; kt++) {
        cp_wait0();
        __syncthreads();
        if (kt + 1 < T) fill(kt + 1, (kt + 1) & 1);

        const uint32_t sa = ST0 + (kt & 1) * STAGE;
        const uint32_t sb = sa + 16384;

#pragma unroll
        for (int k = 0; k < 2; k++) {
            const int lch = k * 2 + (lane >> 4);
            uint32_t ah[2][4], al[2][4];
#pragma unroll
            for (int mt = 0; mt < 2; mt++) {
                int mr  = wm * 32 + mt * 16 + (lane & 15);
                uint32_t base = sa + (uint32_t)mr * 128;
                ldmx4(ah[mt], base + (uint32_t)((lch    ) ^ (mr & 7)) * 16);
                ldmx4(al[mt], base + (uint32_t)((lch + 4) ^ (mr & 7)) * 16);
            }
#pragma unroll
            for (int g = 0; g < 2; g++) {
                int nr  = wn * 32 + g * 16 + (lane & 15);
                uint32_t base = sb + (uint32_t)nr * 128;
                uint32_t bh[4], bl[4];
                ldmx4(bh, base + (uint32_t)((lch    ) ^ (nr & 7)) * 16);
                ldmx4(bl, base + (uint32_t)((lch + 4) ^ (nr & 7)) * 16);
#pragma unroll
                for (int mt = 0; mt < 2; mt++)
#pragma unroll
                    for (int o = 0; o < 2; o++) {
                        const int nt = 2 * g + o;
                        mma16816h(acc[mt][nt], ah[mt], bh[o], bh[2 + o]);
                        mma16816h(acc[mt][nt], ah[mt], bl[o], bl[2 + o]);
                        mma16816h(acc[mt][nt], al[mt], bh[o], bh[2 + o]);
                    }
            }
        }
    }

    const int gm0 = m0 + wm * 32;
    const int gn0 = n0 + wn * 32;
#pragma unroll
    for (int mt = 0; mt < 2; mt++) {
#pragma unroll
        for (int nt = 0; nt < 4; nt++) {
            int r  = gm0 + mt * 16 + (lane >> 2);
            int cc = gn0 + nt * 8 + 2 * (lane & 3);
            if (MODE == 0) {
                float* C0 = (float*)C0v + (size_t)b * sCb;
                *(float2*)(C0 + (size_t)r * N + cc) =
                    make_float2(acc[mt][nt][0], acc[mt][nt][1]);
                *(float2*)(C0 + (size_t)(r + 8) * N + cc) =
                    make_float2(acc[mt][nt][2], acc[mt][nt][3]);
            } else {
                __half* CH = (__half*)C0v + (size_t)b * sCb;
                __half* CL = (__half*)C1v + (size_t)b * sCb;
                __half h0, l0, h1, l1;
#pragma unroll
                for (int hh = 0; hh < 2; hh++) {
                    int rr = r + hh * 8;
                    hsplit(acc[mt][nt][2 * hh + 0], h0, l0);
                    hsplit(acc[mt][nt][2 * hh + 1], h1, l1);
                    *(__half2*)(CH + (size_t)rr * N + cc) = __halves2half2(h0, h1);
                    *(__half2*)(CL + (size_t)rr * N + cc) = __halves2half2(l0, l1);
                }
            }
        }
    }
}

// ---------------------------------------------------------------------------
// gemm1x: C[M,N] fp32 = A @ B^T, single fp16 product.
// CTA 128x64, 8 warps (4m x 2n), warp 32x32, BK=64, 2-stage, 3 CTAs/SM.
// Stage 24KB: A 128 rows x 128B (16KB), B 64 rows x 128B (8KB).
// ---------------------------------------------------------------------------
__global__ __launch_bounds__(256, 3) void gemm1x(
    const __half* __restrict__ A, const __half* __restrict__ B,
    float* __restrict__ C, int M, int N, int K,
    size_t sAb, size_t sBb, size_t sCb)
{
    extern __shared__ char smem[];
    const int tid  = threadIdx.x;
    const int wid  = tid >> 5;
    const int lane = tid & 31;
    const int wm   = wid >> 1;
    const int wn   = wid & 1;
    const int m0   = blockIdx.y * 128;
    const int n0   = blockIdx.x * 64;
    const int b    = blockIdx.z;

    A += (size_t)b * sAb;
    B += (size_t)b * sBb;

    uint32_t sbase = (uint32_t)__cvta_generic_to_shared(smem);
    const uint32_t ST0 = (sbase + 1023) & ~1023u;

    const int T = K >> 6;

    const int fc  = tid & 7;
    const int fr0 = tid >> 3;

    auto fill = [&](int kt, int s) {
        const uint32_t sa = ST0 + s * STAGE;
        const uint32_t sb = sa + 16384;
        const int kg = kt * 64 + fc * 8;
#pragma unroll
        for (int i = 0; i < 4; i++) {
            int row = fr0 + i * 32;
            uint32_t so = (uint32_t)row * 128 + (uint32_t)(fc ^ (row & 7)) * 16;
            cp16(sa + so, A + (size_t)(m0 + row) * K + kg);
        }
#pragma unroll
        for (int i = 0; i < 2; i++) {
            int row = fr0 + i * 32;
            uint32_t so = (uint32_t)row * 128 + (uint32_t)(fc ^ (row & 7)) * 16;
            cp16(sb + so, B + (size_t)(n0 + row) * K + kg);
        }
        cp_commit();
    };

    const uint32_t c0 = lane >> 4;
    uint32_t offA[2], offB[2];
#pragma unroll
    for (int mt = 0; mt < 2; mt++) {
        int mr = wm * 32 + mt * 16 + (lane & 15);
        offA[mt] = (uint32_t)mr * 128 + ((c0 ^ (uint32_t)(mr & 7)) * 16);
    }
#pragma unroll
    for (int ng = 0; ng < 2; ng++) {
        int nr = wn * 32 + ng * 16 + (lane & 15);
        offB[ng] = 16384u + (uint32_t)nr * 128 + ((c0 ^ (uint32_t)(nr & 7)) * 16);
    }

    float acc[2][4][4];
#pragma unroll
    for (int mt = 0; mt < 2; mt++)
#pragma unroll
        for (int nt = 0; nt < 4; nt++)
#pragma unroll
            for (int j = 0; j < 4; j++) acc[mt][nt][j] = 0.0f;

    fill(0, 0);

    for (int kt = 0; kt < T; kt++) {
        cp_wait0();
        __syncthreads();
        if (kt + 1 < T) fill(kt + 1, (kt + 1) & 1);

        const uint32_t sa = ST0 + (kt & 1) * STAGE;

#pragma unroll
        for (int ks = 0; ks < 4; ks++) {
            const uint32_t kx = (uint32_t)ks << 5;
            uint32_t a[2][4];
#pragma unroll
            for (int mt = 0; mt < 2; mt++)
                ldmx4(a[mt], (sa + offA[mt]) ^ kx);
#pragma unroll
            for (int ng = 0; ng < 2; ng++) {
                uint32_t bb[4];
                ldmx4(bb, (sa + offB[ng]) ^ kx);
#pragma unroll
                for (int mt = 0; mt < 2; mt++)
#pragma unroll
                    for (int o = 0; o < 2; o++)
                        mma16816h(acc[mt][2 * ng + o], a[mt], bb[o], bb[2 + o]);
            }
        }
    }

    const int gm0 = m0 + wm * 32;
    const int gn0 = n0 + wn * 32;
    float* C0 = C + (size_t)b * sCb;
#pragma unroll
    for (int mt = 0; mt < 2; mt++) {
#pragma unroll
        for (int nt = 0; nt < 4; nt++) {
            int r  = gm0 + mt * 16 + (lane >> 2);
            int cc = gn0 + nt * 8 + 2 * (lane & 3);
            *(float2*)(C0 + (size_t)r * N + cc) =
                make_float2(acc[mt][nt][0], acc[mt][nt][1]);
            *(float2*)(C0 + (size_t)(r + 8) * N + cc) =
                make_float2(acc[mt][nt][2], acc[mt][nt][3]);
        }
    }
}

// ---------------------------------------------------------------------------
// split fp32 -> fp16 hi/lo
// ---------------------------------------------------------------------------
__global__ __launch_bounds__(256) void split_f16(
    const float* __restrict__ x, __half* __restrict__ hi,
    __half* __restrict__ lo, size_t n4)
{
    size_t i = (size_t)blockIdx.x * blockDim.x + threadIdx.x;
    size_t stride = (size_t)gridDim.x * blockDim.x;
    for (; i < n4; i += stride) {
        float4 v = ((const float4*)x)[i];
        __half h0, l0, h1, l1, h2, l2, h3, l3;
        hsplit(v.x, h0, l0); hsplit(v.y, h1, l1);
        hsplit(v.z, h2, l2); hsplit(v.w, h3, l3);
        ((__half2*)hi)[2 * i]     = __halves2half2(h0, h1);
        ((__half2*)hi)[2 * i + 1] = __halves2half2(h2, h3);
        ((__half2*)lo)[2 * i]     = __halves2half2(l0, l1);
        ((__half2*)lo)[2 * i + 1] = __halves2half2(l2, l3);
    }
}

// ---------------------------------------------------------------------------
// transpose to fp16: S[b][n][h] -> T[b][h][n]
// ---------------------------------------------------------------------------
__global__ __launch_bounds__(256) void transpose_f16(
    const float* __restrict__ S, __half* __restrict__ Tt)
{
    __shared__ float t[32][33];
    const int b  = blockIdx.z;
    const int h0 = blockIdx.x * 32;
    const int n0 = blockIdx.y * 32;
    const int tx = threadIdx.x, ty = threadIdx.y;
    const float* Sb = S + (size_t)b * SEQ * HDIM;
#pragma unroll
    for (int i = 0; i < 4; i++) {
        int r = ty + i * 8;
        t[r][tx] = Sb[(size_t)(n0 + r) * HDIM + h0 + tx];
    }
    __syncthreads();
    const size_t obase = (size_t)b * HDIM * SEQ;
#pragma unroll
    for (int i = 0; i < 4; i++) {
        int r = ty + i * 8;
        Tt[obase + (size_t)(h0 + r) * SEQ + n0 + tx] = __float2half_rn(t[tx][r]);
    }
}

// ---------------------------------------------------------------------------
// softmax rows (len 2048) -> fp16 probabilities
// ---------------------------------------------------------------------------
__global__ __launch_bounds__(256) void softmax_f16(
    const float* __restrict__ S, __half* __restrict__ P)
{
    const float* row = S + (size_t)blockIdx.x * SEQ;
    const int tid = threadIdx.x;
    const int lane = tid & 31, wrp = tid >> 5;
    __shared__ float red[8];

    float v[8];
    float4 v0 = *(const float4*)(row + tid * 8);
    float4 v1 = *(const float4*)(row + tid * 8 + 4);
    v[0]=v0.x; v[1]=v0.y; v[2]=v0.z; v[3]=v0.w;
    v[4]=v1.x; v[5]=v1.y; v[6]=v1.z; v[7]=v1.w;

    float m = v[0];
#pragma unroll
    for (int i = 1; i < 8; i++) m = fmaxf(m, v[i]);
#pragma unroll
    for (int o = 16; o > 0; o >>= 1) m = fmaxf(m, __shfl_xor_sync(~0u, m, o));
    if (lane == 0) red[wrp] = m;
    __syncthreads();
    m = red[0];
#pragma unroll
    for (int w = 1; w < 8; w++) m = fmaxf(m, red[w]);
    __syncthreads();

    float s = 0.0f;
#pragma unroll
    for (int i = 0; i < 8; i++) { v[i] = __expf(v[i] - m); s += v[i]; }
#pragma unroll
    for (int o = 16; o > 0; o >>= 1) s += __shfl_xor_sync(~0u, s, o);
    if (lane == 0) red[wrp] = s;
    __syncthreads();
    s = red[0];
#pragma unroll
    for (int w = 1; w < 8; w++) s += red[w];
    float inv = 1.0f / s;

    __half2* ph = (__half2*)(P + (size_t)blockIdx.x * SEQ + tid * 8);
#pragma unroll
    for (int i = 0; i < 4; i++)
        ph[i] = __floats2half2_rn(v[2 * i] * inv, v[2 * i + 1] * inv);
}

// ---------------------------------------------------------------------------
// launch — index 3 (ncu-captured) stays on gemm3x<1> (proj1).
// Hazards: shh last read @4, overwritten @9; sc last read @7, overwritten @10;
// at last read @8, overwritten @12.
// ---------------------------------------------------------------------------
extern "C" void kernel_launch(void* const* d_in, const int* in_sizes, int n_in,
                              void* d_out, int out_size)
{
    const float* S1 = (const float*)d_in[0];
    const float* S2 = (const float*)d_in[1];
    const float* W1 = (const float*)d_in[2];
    const float* W2 = (const float*)d_in[3];

    float* out1 = (float*)d_out;
    float* out2 = out1 + E1;

    __half *s1h, *s1l, *s2h, *s2l, *w1h, *w1l, *w2h, *w2l, *shh, *shl;
    __half *s1t, *s2t, *at;
    float* sc;
    cudaGetSymbolAddress((void**)&s1h, g_s1h);
    cudaGetSymbolAddress((void**)&s1l, g_s1l);
    cudaGetSymbolAddress((void**)&s2h, g_s2h);
    cudaGetSymbolAddress((void**)&s2l, g_s2l);
    cudaGetSymbolAddress((void**)&w1h, g_w1h);
    cudaGetSymbolAddress((void**)&w1l, g_w1l);
    cudaGetSymbolAddress((void**)&w2h, g_w2h);
    cudaGetSymbolAddress((void**)&w2l, g_w2l);
    cudaGetSymbolAddress((void**)&shh, g_shh);
    cudaGetSymbolAddress((void**)&shl, g_shl);
    cudaGetSymbolAddress((void**)&s1t, g_s1t);
    cudaGetSymbolAddress((void**)&s2t, g_s2t);
    cudaGetSymbolAddress((void**)&sc,  g_sc);
    cudaGetSymbolAddress((void**)&at,  g_at);

    cudaFuncSetAttribute(gemm3x<0>, cudaFuncAttributeMaxDynamicSharedMemorySize, SMEM_REQ);
    cudaFuncSetAttribute(gemm3x<1>, cudaFuncAttributeMaxDynamicSharedMemorySize, SMEM_REQ);
    cudaFuncSetAttribute(gemm1x,    cudaFuncAttributeMaxDynamicSharedMemorySize, SMEM_REQ);

    const size_t sS  = (size_t)SEQ * HDIM;
    const size_t sSc = (size_t)SEQ * SEQ;

    dim3 blk(256);
    dim3 gProj(HDIM / 64, SEQ / 128, BATCH);    // N=1024, M=2048
    dim3 gScore(SEQ / 64, SEQ / 128, BATCH);    // N=2048, M=2048
    dim3 gPV(HDIM / 64, SEQ / 128, BATCH);      // N=1024, M=2048, K=2048
    dim3 tb(32, 8);
    dim3 tg(HDIM / 32, SEQ / 32, BATCH);

    split_f16<<<2048, 256>>>(S2, s2h, s2l, E1 / 4);                  // 0
    split_f16<<<512,  256>>>(W1, w1h, w1l, EW / 4);                  // 1
    split_f16<<<2048, 256>>>(S1, s1h, s1l, E1 / 4);                  // 2

    gemm3x<1><<<gProj, blk, SMEM_REQ>>>(                             // 3 (ncu)
        s2h, s2l, w1h, w1l, shh, shl, SEQ, HDIM, HDIM, sS, 0, sS);
    gemm3x<0><<<gScore, blk, SMEM_REQ>>>(                            // 4
        s1h, s1l, shh, shl, sc, nullptr, SEQ, SEQ, HDIM, sS, sS, sSc);

    split_f16<<<512,  256>>>(W2, w2h, w2l, EW / 4);                  // 5
    transpose_f16<<<tg, tb>>>(S2, s2t);                              // 6
    softmax_f16<<<BATCH * SEQ, 256>>>(sc, at);                       // 7
    gemm1x<<<gPV, blk, SMEM_REQ>>>(                                  // 8
        at, s2t, out1, SEQ, HDIM, SEQ, sSc, sS, sS);

    gemm3x<1><<<gProj, blk, SMEM_REQ>>>(                             // 9
        s1h, s1l, w2h, w2l, shh, shl, SEQ, HDIM, HDIM, sS, 0, sS);
    gemm3x<0><<<gScore, blk, SMEM_REQ>>>(                            // 10
        s2h, s2l, shh, shl, sc, nullptr, SEQ, SEQ, HDIM, sS, sS, sSc);
    transpose_f16<<<tg, tb>>>(S1, s1t);                              // 11
    softmax_f16<<<BATCH * SEQ, 256>>>(sc, at);                       // 12
    gemm1x<<<gPV, blk, SMEM_REQ>>>(                                  // 13
        at, s1t, out2, SEQ, HDIM, SEQ, sSc, sS, sS);
}

// round 16
// speedup vs baseline: 1.0651x; 1.0651x over previous
#include <cuda_runtime.h>
#include <cuda_bf16.h>
#include <cuda_fp16.h>
#include <cstdint>
#include <cstddef>

// ---------------------------------------------------------------------------
// BiAffine, sm_100 base target (no tcgen05 at this compile target).
//   dir1: Sh = S2@W1^T ; sc = S1@Sh^T ; P = softmax(sc) ; out1 = P@S2
//   dir2: Sh = S1@W2^T ; sc = S2@Sh^T ; P = softmax(sc) ; out2 = P@S1
// proj/scores: fp16 hi/lo 3-product mma.sync. PV: single fp16 product.
// R16: issue-port attack. Pipes sum to ~98% (tensor 57 + fma 14 + alu 26)
// in every config -> dispatch-saturated. Cut integer work in the mainloop:
//   (a) fill addressing hoisted to 8 persistent row pointers (+64B/chunk),
//   (b) ldmatrix offsets precomputed, k-step/lo via XOR folds.
// Tile config = R12 best (128x128, warp 32x64, 3-stage, 2 CTA/SM).
// ---------------------------------------------------------------------------

#define BATCH 8
#define SEQ   2048
#define HDIM  1024

#define E1 ((size_t)BATCH * SEQ * HDIM)   // 16777216
#define EW ((size_t)HDIM * HDIM)          // 1048576
#define ES ((size_t)BATCH * SEQ * SEQ)    // 33554432

// ---- static scratch (no allocations allowed) ------------------------------
__device__ __half g_s1h[E1], g_s1l[E1], g_s2h[E1], g_s2l[E1];
__device__ __half g_w1h[EW], g_w1l[EW], g_w2h[EW], g_w2l[EW];
__device__ __half g_shh[E1], g_shl[E1];
__device__ __half g_s1t[E1], g_s2t[E1];   // transposed S, fp16
__device__ float  g_sc[ES];
__device__ __half g_at[ES];               // softmax probs, fp16

// ---------------------------------------------------------------------------
// helpers
// ---------------------------------------------------------------------------
__device__ __forceinline__ void cp16(uint32_t s, const void* g) {
    asm volatile("cp.async.cg.shared.global [%0], [%1], 16;" :: "r"(s), "l"(g));
}
__device__ __forceinline__ void cp_commit() {
    asm volatile("cp.async.commit_group;");
}
__device__ __forceinline__ void cp_wait1() {
    asm volatile("cp.async.wait_group 1;");
}

__device__ __forceinline__ void ldmx4(uint32_t* r, uint32_t addr) {
    asm volatile("ldmatrix.sync.aligned.m8n8.x4.shared.b16 {%0,%1,%2,%3}, [%4];"
                 : "=r"(r[0]), "=r"(r[1]), "=r"(r[2]), "=r"(r[3]) : "r"(addr));
}

__device__ __forceinline__ void mma16816h(float* c, const uint32_t* a,
                                          uint32_t b0, uint32_t b1) {
    asm volatile(
        "mma.sync.aligned.m16n8k16.row.col.f32.f16.f16.f32 "
        "{%0,%1,%2,%3}, {%4,%5,%6,%7}, {%8,%9}, {%0,%1,%2,%3};"
        : "+f"(c[0]), "+f"(c[1]), "+f"(c[2]), "+f"(c[3])
        : "r"(a[0]), "r"(a[1]), "r"(a[2]), "r"(a[3]), "r"(b0), "r"(b1));
}

__device__ __forceinline__ void hsplit(float x, __half& h, __half& l) {
    h = __float2half_rn(x);
    l = __float2half_rn(x - __half2float(h));
}

// ---------------------------------------------------------------------------
// gemm3x: C = Ah@Bh^T + Ah@Bl^T + Al@Bh^T  (fp16 hi/lo)
// CTA 128x128, 8 warps (4m x 2n), warp 32x64, BK=32, 3-stage, 2 CTAs/SM.
// MODE 0: C0 = fp32. MODE 1: C0 = fp16 hi, C1 = fp16 lo.
// ---------------------------------------------------------------------------
#define STAGE 32768
#define NSTG  3
#define SMEM_REQ (NSTG * STAGE + 1024)

template <int MODE>
__global__ __launch_bounds__(256, 2) void gemm3x(
    const __half* __restrict__ Ah, const __half* __restrict__ Al,
    const __half* __restrict__ Bh, const __half* __restrict__ Bl,
    void* __restrict__ C0v, void* __restrict__ C1v,
    int M, int N, int K, size_t sAb, size_t sBb, size_t sCb)
{
    extern __shared__ char smem[];
    const int tid  = threadIdx.x;
    const int wid  = tid >> 5;
    const int lane = tid & 31;
    const int wm   = wid >> 1;
    const int wn   = wid & 1;
    const int m0   = blockIdx.y * 128;
    const int n0   = blockIdx.x * 128;
    const int b    = blockIdx.z;

    uint32_t sbase = (uint32_t)__cvta_generic_to_shared(smem);
    const uint32_t ST0 = (sbase + 1023) & ~1023u;

    const int T = K >> 5;

    // ---- fill addressing: hoisted persistent pointers ----
    const int fc  = tid & 7;        // 16B chunk 0..7
    const int fr0 = tid >> 3;       // 0..31
    const __half* baseA = ((fc < 4) ? Ah : Al) + (size_t)b * sAb;
    const __half* baseB = ((fc < 4) ? Bh : Bl) + (size_t)b * sBb;
    const int kg0 = (fc & 3) * 8;

    const __half* pA[4];
    const __half* pB[4];
    uint32_t so[4];
#pragma unroll
    for (int i = 0; i < 4; i++) {
        int row = fr0 + i * 32;
        pA[i] = baseA + (size_t)(m0 + row) * K + kg0;
        pB[i] = baseB + (size_t)(n0 + row) * K + kg0;
        so[i] = (uint32_t)row * 128 + (uint32_t)(fc ^ (row & 7)) * 16;
    }

    auto fill = [&](int s) {
        const uint32_t sa = ST0 + s * STAGE;
#pragma unroll
        for (int i = 0; i < 4; i++) {
            cp16(sa + so[i],          pA[i]);
            cp16(sa + so[i] + 16384u, pB[i]);
            pA[i] += 32;            // next K chunk (64 bytes)
            pB[i] += 32;
        }
        cp_commit();
    };

    // ---- ldmatrix addressing: precomputed offsets + XOR folds ----
    const uint32_t c0l = lane >> 4;
    uint32_t offA[2], offB[4];
#pragma unroll
    for (int mt = 0; mt < 2; mt++) {
        int mr = wm * 32 + mt * 16 + (lane & 15);
        offA[mt] = (uint32_t)mr * 128 + ((c0l ^ (uint32_t)(mr & 7)) * 16);
    }
#pragma unroll
    for (int ng = 0; ng < 4; ng++) {
        int nr = wn * 64 + ng * 16 + (lane & 15);
        offB[ng] = 16384u + (uint32_t)nr * 128 + ((c0l ^ (uint32_t)(nr & 7)) * 16);
    }

    float acc[2][8][4];
#pragma unroll
    for (int mt = 0; mt < 2; mt++)
#pragma unroll
        for (int nt = 0; nt < 8; nt++)
#pragma unroll
            for (int j = 0; j < 4; j++) acc[mt][nt][j] = 0.0f;

    fill(0); fill(1);

    int scur = 0, snext2 = 2;
    for (int kt = 0; kt < T; kt++) {
        cp_wait1();
        __syncthreads();
        if (kt + 2 < T) fill(snext2); else cp_commit();

        const uint32_t sa = ST0 + scur * STAGE;
        scur = (scur == 2) ? 0 : scur + 1;
        snext2 = (snext2 == 2) ? 0 : snext2 + 1;

#pragma unroll
        for (int k = 0; k < 2; k++) {
            const uint32_t kx = (uint32_t)k << 5;
            uint32_t ah[2][4], al[2][4];
#pragma unroll
            for (int mt = 0; mt < 2; mt++) {
                uint32_t a0 = (sa + offA[mt]) ^ kx;
                ldmx4(ah[mt], a0);
                ldmx4(al[mt], a0 ^ 0x40u);
            }
#pragma unroll
            for (int ng = 0; ng < 4; ng++) {
                uint32_t b0 = (sa + offB[ng]) ^ kx;
                uint32_t bh[4], bl[4];
                ldmx4(bh, b0);
                ldmx4(bl, b0 ^ 0x40u);
#pragma unroll
                for (int mt = 0; mt < 2; mt++)
#pragma unroll
                    for (int o = 0; o < 2; o++) {
                        const int nt = 2 * ng + o;
                        mma16816h(acc[mt][nt], ah[mt], bh[o], bh[2 + o]);
                        mma16816h(acc[mt][nt], ah[mt], bl[o], bl[2 + o]);
                        mma16816h(acc[mt][nt], al[mt], bh[o], bh[2 + o]);
                    }
            }
        }
    }

    const int gm0 = m0 + wm * 32;
    const int gn0 = n0 + wn * 64;
#pragma unroll
    for (int mt = 0; mt < 2; mt++) {
#pragma unroll
        for (int nt = 0; nt < 8; nt++) {
            int r  = gm0 + mt * 16 + (lane >> 2);
            int cc = gn0 + nt * 8 + 2 * (lane & 3);
            if (MODE == 0) {
                float* C0 = (float*)C0v + (size_t)b * sCb;
                *(float2*)(C0 + (size_t)r * N + cc) =
                    make_float2(acc[mt][nt][0], acc[mt][nt][1]);
                *(float2*)(C0 + (size_t)(r + 8) * N + cc) =
                    make_float2(acc[mt][nt][2], acc[mt][nt][3]);
            } else {
                __half* CH = (__half*)C0v + (size_t)b * sCb;
                __half* CL = (__half*)C1v + (size_t)b * sCb;
                __half h0, l0, h1, l1;
#pragma unroll
                for (int hh = 0; hh < 2; hh++) {
                    int rr = r + hh * 8;
                    hsplit(acc[mt][nt][2 * hh + 0], h0, l0);
                    hsplit(acc[mt][nt][2 * hh + 1], h1, l1);
                    *(__half2*)(CH + (size_t)rr * N + cc) = __halves2half2(h0, h1);
                    *(__half2*)(CL + (size_t)rr * N + cc) = __halves2half2(l0, l1);
                }
            }
        }
    }
}

// ---------------------------------------------------------------------------
// gemm1x: C[M,N] fp32 = A @ B^T, single fp16 product.
// CTA 128x128, warp 32x64, BK=64, 3-stage, 2 CTAs/SM. Fill pointers hoisted.
// ---------------------------------------------------------------------------
__global__ __launch_bounds__(256, 2) void gemm1x(
    const __half* __restrict__ A, const __half* __restrict__ B,
    float* __restrict__ C, int M, int N, int K,
    size_t sAb, size_t sBb, size_t sCb)
{
    extern __shared__ char smem[];
    const int tid  = threadIdx.x;
    const int wid  = tid >> 5;
    const int lane = tid & 31;
    const int wm   = wid >> 1;
    const int wn   = wid & 1;
    const int m0   = blockIdx.y * 128;
    const int n0   = blockIdx.x * 128;
    const int b    = blockIdx.z;

    uint32_t sbase = (uint32_t)__cvta_generic_to_shared(smem);
    const uint32_t ST0 = (sbase + 1023) & ~1023u;

    const int T = K >> 6;

    const int fc  = tid & 7;
    const int fr0 = tid >> 3;
    const __half* baseA = A + (size_t)b * sAb;
    const __half* baseB = B + (size_t)b * sBb;
    const int kg0 = fc * 8;

    const __half* pA[4];
    const __half* pB[4];
    uint32_t so[4];
#pragma unroll
    for (int i = 0; i < 4; i++) {
        int row = fr0 + i * 32;
        pA[i] = baseA + (size_t)(m0 + row) * K + kg0;
        pB[i] = baseB + (size_t)(n0 + row) * K + kg0;
        so[i] = (uint32_t)row * 128 + (uint32_t)(fc ^ (row & 7)) * 16;
    }

    auto fill = [&](int s) {
        const uint32_t sa = ST0 + s * STAGE;
#pragma unroll
        for (int i = 0; i < 4; i++) {
            cp16(sa + so[i],          pA[i]);
            cp16(sa + so[i] + 16384u, pB[i]);
            pA[i] += 64;            // next K chunk (128 bytes)
            pB[i] += 64;
        }
        cp_commit();
    };

    const uint32_t c0 = lane >> 4;
    uint32_t offA[2], offB[4];
#pragma unroll
    for (int mt = 0; mt < 2; mt++) {
        int mr = wm * 32 + mt * 16 + (lane & 15);
        offA[mt] = (uint32_t)mr * 128 + ((c0 ^ (uint32_t)(mr & 7)) * 16);
    }
#pragma unroll
    for (int ng = 0; ng < 4; ng++) {
        int nr = wn * 64 + ng * 16 + (lane & 15);
        offB[ng] = 16384u + (uint32_t)nr * 128 + ((c0 ^ (uint32_t)(nr & 7)) * 16);
    }

    float acc[2][8][4];
#pragma unroll
    for (int mt = 0; mt < 2; mt++)
#pragma unroll
        for (int nt = 0; nt < 8; nt++)
#pragma unroll
            for (int j = 0; j < 4; j++) acc[mt][nt][j] = 0.0f;

    fill(0); fill(1);

    int scur = 0, snext2 = 2;
    for (int kt = 0; kt < T; kt++) {
        cp_wait1();
        __syncthreads();
        if (kt + 2 < T) fill(snext2); else cp_commit();

        const uint32_t sa = ST0 + scur * STAGE;
        scur = (scur == 2) ? 0 : scur + 1;
        snext2 = (snext2 == 2) ? 0 : snext2 + 1;

#pragma unroll
        for (int ks = 0; ks < 4; ks++) {
            const uint32_t kx = (uint32_t)ks << 5;
            uint32_t a[2][4];
#pragma unroll
            for (int mt = 0; mt < 2; mt++)
                ldmx4(a[mt], (sa + offA[mt]) ^ kx);
#pragma unroll
            for (int ng = 0; ng < 4; ng++) {
                uint32_t bb[4];
                ldmx4(bb, (sa + offB[ng]) ^ kx);
#pragma unroll
                for (int mt = 0; mt < 2; mt++)
#pragma unroll
                    for (int o = 0; o < 2; o++)
                        mma16816h(acc[mt][2 * ng + o], a[mt], bb[o], bb[2 + o]);
            }
        }
    }

    const int gm0 = m0 + wm * 32;
    const int gn0 = n0 + wn * 64;
    float* C0 = C + (size_t)b * sCb;
#pragma unroll
    for (int mt = 0; mt < 2; mt++) {
#pragma unroll
        for (int nt = 0; nt < 8; nt++) {
            int r  = gm0 + mt * 16 + (lane >> 2);
            int cc = gn0 + nt * 8 + 2 * (lane & 3);
            *(float2*)(C0 + (size_t)r * N + cc) =
                make_float2(acc[mt][nt][0], acc[mt][nt][1]);
            *(float2*)(C0 + (size_t)(r + 8) * N + cc) =
                make_float2(acc[mt][nt][2], acc[mt][nt][3]);
        }
    }
}

// ---------------------------------------------------------------------------
// split fp32 -> fp16 hi/lo
// ---------------------------------------------------------------------------
__global__ __launch_bounds__(256) void split_f16(
    const float* __restrict__ x, __half* __restrict__ hi,
    __half* __restrict__ lo, size_t n4)
{
    size_t i = (size_t)blockIdx.x * blockDim.x + threadIdx.x;
    size_t stride = (size_t)gridDim.x * blockDim.x;
    for (; i < n4; i += stride) {
        float4 v = ((const float4*)x)[i];
        __half h0, l0, h1, l1, h2, l2, h3, l3;
        hsplit(v.x, h0, l0); hsplit(v.y, h1, l1);
        hsplit(v.z, h2, l2); hsplit(v.w, h3, l3);
        ((__half2*)hi)[2 * i]     = __halves2half2(h0, h1);
        ((__half2*)hi)[2 * i + 1] = __halves2half2(h2, h3);
        ((__half2*)lo)[2 * i]     = __halves2half2(l0, l1);
        ((__half2*)lo)[2 * i + 1] = __halves2half2(l2, l3);
    }
}

// ---------------------------------------------------------------------------
// transpose to fp16: S[b][n][h] -> T[b][h][n]
// ---------------------------------------------------------------------------
__global__ __launch_bounds__(256) void transpose_f16(
    const float* __restrict__ S, __half* __restrict__ Tt)
{
    __shared__ float t[32][33];
    const int b  = blockIdx.z;
    const int h0 = blockIdx.x * 32;
    const int n0 = blockIdx.y * 32;
    const int tx = threadIdx.x, ty = threadIdx.y;
    const float* Sb = S + (size_t)b * SEQ * HDIM;
#pragma unroll
    for (int i = 0; i < 4; i++) {
        int r = ty + i * 8;
        t[r][tx] = Sb[(size_t)(n0 + r) * HDIM + h0 + tx];
    }
    __syncthreads();
    const size_t obase = (size_t)b * HDIM * SEQ;
#pragma unroll
    for (int i = 0; i < 4; i++) {
        int r = ty + i * 8;
        Tt[obase + (size_t)(h0 + r) * SEQ + n0 + tx] = __float2half_rn(t[tx][r]);
    }
}

// ---------------------------------------------------------------------------
// softmax rows (len 2048) -> fp16 probabilities
// ---------------------------------------------------------------------------
__global__ __launch_bounds__(256) void softmax_f16(
    const float* __restrict__ S, __half* __restrict__ P)
{
    const float* row = S + (size_t)blockIdx.x * SEQ;
    const int tid = threadIdx.x;
    const int lane = tid & 31, wrp = tid >> 5;
    __shared__ float red[8];

    float v[8];
    float4 v0 = *(const float4*)(row + tid * 8);
    float4 v1 = *(const float4*)(row + tid * 8 + 4);
    v[0]=v0.x; v[1]=v0.y; v[2]=v0.z; v[3]=v0.w;
    v[4]=v1.x; v[5]=v1.y; v[6]=v1.z; v[7]=v1.w;

    float m = v[0];
#pragma unroll
    for (int i = 1; i < 8; i++) m = fmaxf(m, v[i]);
#pragma unroll
    for (int o = 16; o > 0; o >>= 1) m = fmaxf(m, __shfl_xor_sync(~0u, m, o));
    if (lane == 0) red[wrp] = m;
    __syncthreads();
    m = red[0];
#pragma unroll
    for (int w = 1; w < 8; w++) m = fmaxf(m, red[w]);
    __syncthreads();

    float s = 0.0f;
#pragma unroll
    for (int i = 0; i < 8; i++) { v[i] = __expf(v[i] - m); s += v[i]; }
#pragma unroll
    for (int o = 16; o > 0; o >>= 1) s += __shfl_xor_sync(~0u, s, o);
    if (lane == 0) red[wrp] = s;
    __syncthreads();
    s = red[0];
#pragma unroll
    for (int w = 1; w < 8; w++) s += red[w];
    float inv = 1.0f / s;

    __half2* ph = (__half2*)(P + (size_t)blockIdx.x * SEQ + tid * 8);
#pragma unroll
    for (int i = 0; i < 4; i++)
        ph[i] = __floats2half2_rn(v[2 * i] * inv, v[2 * i + 1] * inv);
}

// ---------------------------------------------------------------------------
// launch — index 3 (ncu-captured) stays on gemm3x<1> (proj1).
// Hazards: shh last read @4, overwritten @9; sc last read @7, overwritten @10;
// at last read @8, overwritten @12.
// ---------------------------------------------------------------------------
extern "C" void kernel_launch(void* const* d_in, const int* in_sizes, int n_in,
                              void* d_out, int out_size)
{
    const float* S1 = (const float*)d_in[0];
    const float* S2 = (const float*)d_in[1];
    const float* W1 = (const float*)d_in[2];
    const float* W2 = (const float*)d_in[3];

    float* out1 = (float*)d_out;
    float* out2 = out1 + E1;

    __half *s1h, *s1l, *s2h, *s2l, *w1h, *w1l, *w2h, *w2l, *shh, *shl;
    __half *s1t, *s2t, *at;
    float* sc;
    cudaGetSymbolAddress((void**)&s1h, g_s1h);
    cudaGetSymbolAddress((void**)&s1l, g_s1l);
    cudaGetSymbolAddress((void**)&s2h, g_s2h);
    cudaGetSymbolAddress((void**)&s2l, g_s2l);
    cudaGetSymbolAddress((void**)&w1h, g_w1h);
    cudaGetSymbolAddress((void**)&w1l, g_w1l);
    cudaGetSymbolAddress((void**)&w2h, g_w2h);
    cudaGetSymbolAddress((void**)&w2l, g_w2l);
    cudaGetSymbolAddress((void**)&shh, g_shh);
    cudaGetSymbolAddress((void**)&shl, g_shl);
    cudaGetSymbolAddress((void**)&s1t, g_s1t);
    cudaGetSymbolAddress((void**)&s2t, g_s2t);
    cudaGetSymbolAddress((void**)&sc,  g_sc);
    cudaGetSymbolAddress((void**)&at,  g_at);

    cudaFuncSetAttribute(gemm3x<0>, cudaFuncAttributeMaxDynamicSharedMemorySize, SMEM_REQ);
    cudaFuncSetAttribute(gemm3x<1>, cudaFuncAttributeMaxDynamicSharedMemorySize, SMEM_REQ);
    cudaFuncSetAttribute(gemm1x,    cudaFuncAttributeMaxDynamicSharedMemorySize, SMEM_REQ);

    const size_t sS  = (size_t)SEQ * HDIM;
    const size_t sSc = (size_t)SEQ * SEQ;

    dim3 blk(256);
    dim3 gProj(HDIM / 128, SEQ / 128, BATCH);
    dim3 gScore(SEQ / 128, SEQ / 128, BATCH);
    dim3 gPV(HDIM / 128, SEQ / 128, BATCH);
    dim3 tb(32, 8);
    dim3 tg(HDIM / 32, SEQ / 32, BATCH);

    split_f16<<<2048, 256>>>(S2, s2h, s2l, E1 / 4);                  // 0
    split_f16<<<512,  256>>>(W1, w1h, w1l, EW / 4);                  // 1
    split_f16<<<2048, 256>>>(S1, s1h, s1l, E1 / 4);                  // 2

    gemm3x<1><<<gProj, blk, SMEM_REQ>>>(                             // 3 (ncu)
        s2h, s2l, w1h, w1l, shh, shl, SEQ, HDIM, HDIM, sS, 0, sS);
    gemm3x<0><<<gScore, blk, SMEM_REQ>>>(                            // 4
        s1h, s1l, shh, shl, sc, nullptr, SEQ, SEQ, HDIM, sS, sS, sSc);

    split_f16<<<512,  256>>>(W2, w2h, w2l, EW / 4);                  // 5
    transpose_f16<<<tg, tb>>>(S2, s2t);                              // 6
    softmax_f16<<<BATCH * SEQ, 256>>>(sc, at);                       // 7
    gemm1x<<<gPV, blk, SMEM_REQ>>>(                                  // 8
        at, s2t, out1, SEQ, HDIM, SEQ, sSc, sS, sS);

    gemm3x<1><<<gProj, blk, SMEM_REQ>>>(                             // 9
        s1h, s1l, w2h, w2l, shh, shl, SEQ, HDIM, HDIM, sS, 0, sS);
    gemm3x<0><<<gScore, blk, SMEM_REQ>>>(                            // 10
        s2h, s2l, shh, shl, sc, nullptr, SEQ, SEQ, HDIM, sS, sS, sSc);
    transpose_f16<<<tg, tb>>>(S1, s1t);                              // 11
    softmax_f16<<<BATCH * SEQ, 256>>>(sc, at);                       // 12
    gemm1x<<<gPV, blk, SMEM_REQ>>>(                                  // 13
        at, s1t, out2, SEQ, HDIM, SEQ, sSc, sS, sS);
}

// round 17
// speedup vs baseline: 1.1102x; 1.0423x over previous
#include <cuda_runtime.h>
#include <cuda_bf16.h>
#include <cuda_fp16.h>
#include <cstdint>
#include <cstddef>

// ---------------------------------------------------------------------------
// BiAffine, sm_100 base target (no tcgen05 at this compile target).
//   dir1: Sh1 = S2@W1^T ; sc1 = S1@Sh1^T ; P1 = softmax(sc1) ; out1 = P1@S2
//   dir2: Sh2 = S1@W2^T ; sc2 = S2@Sh2^T ; P2 = softmax(sc2) ; out2 = P2@S1
// proj/scores: fp16 hi/lo 3-product mma.sync (R16 mainloop, unchanged).
// PV: single-product fp16 mma.sync.
// R17: both directions batched into single kernels via blockIdx.z (halves
// wave-quantization tails, 14 -> 7 launches), split+transpose fused for S,
// W splits and softmaxes merged. GEMM inner loops byte-equivalent to R16.
// ---------------------------------------------------------------------------

#define BATCH 8
#define SEQ   2048
#define HDIM  1024

#define E1 ((size_t)BATCH * SEQ * HDIM)   // 16777216
#define EW ((size_t)HDIM * HDIM)          // 1048576
#define ES ((size_t)BATCH * SEQ * SEQ)    // 33554432

// ---- static scratch (no allocations allowed) ------------------------------
__device__ __half g_s1h[E1], g_s1l[E1], g_s2h[E1], g_s2l[E1];
__device__ __half g_w1h[EW], g_w1l[EW], g_w2h[EW], g_w2l[EW];
__device__ __half g_sh1h[E1], g_sh1l[E1], g_sh2h[E1], g_sh2l[E1];
__device__ __half g_s1t[E1], g_s2t[E1];       // transposed S, fp16
__device__ float  g_sc[2 * ES];               // scores, both dirs
__device__ __half g_at[2 * ES];               // softmax probs, both dirs

// ---------------------------------------------------------------------------
// helpers
// ---------------------------------------------------------------------------
__device__ __forceinline__ void cp16(uint32_t s, const void* g) {
    asm volatile("cp.async.cg.shared.global [%0], [%1], 16;" :: "r"(s), "l"(g));
}
__device__ __forceinline__ void cp_commit() {
    asm volatile("cp.async.commit_group;");
}
__device__ __forceinline__ void cp_wait1() {
    asm volatile("cp.async.wait_group 1;");
}

__device__ __forceinline__ void ldmx4(uint32_t* r, uint32_t addr) {
    asm volatile("ldmatrix.sync.aligned.m8n8.x4.shared.b16 {%0,%1,%2,%3}, [%4];"
                 : "=r"(r[0]), "=r"(r[1]), "=r"(r[2]), "=r"(r[3]) : "r"(addr));
}

__device__ __forceinline__ void mma16816h(float* c, const uint32_t* a,
                                          uint32_t b0, uint32_t b1) {
    asm volatile(
        "mma.sync.aligned.m16n8k16.row.col.f32.f16.f16.f32 "
        "{%0,%1,%2,%3}, {%4,%5,%6,%7}, {%8,%9}, {%0,%1,%2,%3};"
        : "+f"(c[0]), "+f"(c[1]), "+f"(c[2]), "+f"(c[3])
        : "r"(a[0]), "r"(a[1]), "r"(a[2]), "r"(a[3]), "r"(b0), "r"(b1));
}

__device__ __forceinline__ void hsplit(float x, __half& h, __half& l) {
    h = __float2half_rn(x);
    l = __float2half_rn(x - __half2float(h));
}

#define STAGE 32768
#define NSTG  3
#define SMEM_REQ (NSTG * STAGE + 1024)

// ---------------------------------------------------------------------------
// gemm3 body (R16 mainloop): C = Ah@Bh^T + Ah@Bl^T + Al@Bh^T  (fp16 hi/lo)
// CTA 128x128, 8 warps (4m x 2n), warp 32x64, BK=32, 3-stage, 2 CTAs/SM.
// Pointers pre-offset by batch. NN, KK compile-time.
// MODE 0: write fp32 C0. MODE 1: write fp16 hi CH / lo CL.
// ---------------------------------------------------------------------------
template <int MODE, int NN, int KK>
__device__ __forceinline__ void gemm3_run(
    char* smem,
    const __half* __restrict__ Ah, const __half* __restrict__ Al,
    const __half* __restrict__ Bh, const __half* __restrict__ Bl,
    float* __restrict__ C0f, __half* __restrict__ CH, __half* __restrict__ CL)
{
    const int tid  = threadIdx.x;
    const int wid  = tid >> 5;
    const int lane = tid & 31;
    const int wm   = wid >> 1;
    const int wn   = wid & 1;
    const int m0   = blockIdx.y * 128;
    const int n0   = blockIdx.x * 128;

    uint32_t sbase = (uint32_t)__cvta_generic_to_shared(smem);
    const uint32_t ST0 = (sbase + 1023) & ~1023u;

    constexpr int T = KK >> 5;

    const int fc  = tid & 7;
    const int fr0 = tid >> 3;
    const __half* baseA = (fc < 4) ? Ah : Al;
    const __half* baseB = (fc < 4) ? Bh : Bl;
    const int kg0 = (fc & 3) * 8;

    const __half* pA[4];
    const __half* pB[4];
    uint32_t so[4];
#pragma unroll
    for (int i = 0; i < 4; i++) {
        int row = fr0 + i * 32;
        pA[i] = baseA + (size_t)(m0 + row) * KK + kg0;
        pB[i] = baseB + (size_t)(n0 + row) * KK + kg0;
        so[i] = (uint32_t)row * 128 + (uint32_t)(fc ^ (row & 7)) * 16;
    }

    auto fill = [&](int s) {
        const uint32_t sa = ST0 + s * STAGE;
#pragma unroll
        for (int i = 0; i < 4; i++) {
            cp16(sa + so[i],          pA[i]);
            cp16(sa + so[i] + 16384u, pB[i]);
            pA[i] += 32;
            pB[i] += 32;
        }
        cp_commit();
    };

    const uint32_t c0l = lane >> 4;
    uint32_t offA[2], offB[4];
#pragma unroll
    for (int mt = 0; mt < 2; mt++) {
        int mr = wm * 32 + mt * 16 + (lane & 15);
        offA[mt] = (uint32_t)mr * 128 + ((c0l ^ (uint32_t)(mr & 7)) * 16);
    }
#pragma unroll
    for (int ng = 0; ng < 4; ng++) {
        int nr = wn * 64 + ng * 16 + (lane & 15);
        offB[ng] = 16384u + (uint32_t)nr * 128 + ((c0l ^ (uint32_t)(nr & 7)) * 16);
    }

    float acc[2][8][4];
#pragma unroll
    for (int mt = 0; mt < 2; mt++)
#pragma unroll
        for (int nt = 0; nt < 8; nt++)
#pragma unroll
            for (int j = 0; j < 4; j++) acc[mt][nt][j] = 0.0f;

    fill(0); fill(1);

    int scur = 0, snext2 = 2;
    for (int kt = 0; kt < T; kt++) {
        cp_wait1();
        __syncthreads();
        if (kt + 2 < T) fill(snext2); else cp_commit();

        const uint32_t sa = ST0 + scur * STAGE;
        scur = (scur == 2) ? 0 : scur + 1;
        snext2 = (snext2 == 2) ? 0 : snext2 + 1;

#pragma unroll
        for (int k = 0; k < 2; k++) {
            const uint32_t kx = (uint32_t)k << 5;
            uint32_t ah[2][4], al[2][4];
#pragma unroll
            for (int mt = 0; mt < 2; mt++) {
                uint32_t a0 = (sa + offA[mt]) ^ kx;
                ldmx4(ah[mt], a0);
                ldmx4(al[mt], a0 ^ 0x40u);
            }
#pragma unroll
            for (int ng = 0; ng < 4; ng++) {
                uint32_t b0 = (sa + offB[ng]) ^ kx;
                uint32_t bh[4], bl[4];
                ldmx4(bh, b0);
                ldmx4(bl, b0 ^ 0x40u);
#pragma unroll
                for (int mt = 0; mt < 2; mt++)
#pragma unroll
                    for (int o = 0; o < 2; o++) {
                        const int nt = 2 * ng + o;
                        mma16816h(acc[mt][nt], ah[mt], bh[o], bh[2 + o]);
                        mma16816h(acc[mt][nt], ah[mt], bl[o], bl[2 + o]);
                        mma16816h(acc[mt][nt], al[mt], bh[o], bh[2 + o]);
                    }
            }
        }
    }

    const int gm0 = m0 + wm * 32;
    const int gn0 = n0 + wn * 64;
#pragma unroll
    for (int mt = 0; mt < 2; mt++) {
#pragma unroll
        for (int nt = 0; nt < 8; nt++) {
            int r  = gm0 + mt * 16 + (lane >> 2);
            int cc = gn0 + nt * 8 + 2 * (lane & 3);
            if (MODE == 0) {
                *(float2*)(C0f + (size_t)r * NN + cc) =
                    make_float2(acc[mt][nt][0], acc[mt][nt][1]);
                *(float2*)(C0f + (size_t)(r + 8) * NN + cc) =
                    make_float2(acc[mt][nt][2], acc[mt][nt][3]);
            } else {
                __half h0, l0, h1, l1;
#pragma unroll
                for (int hh = 0; hh < 2; hh++) {
                    int rr = r + hh * 8;
                    hsplit(acc[mt][nt][2 * hh + 0], h0, l0);
                    hsplit(acc[mt][nt][2 * hh + 1], h1, l1);
                    *(__half2*)(CH + (size_t)rr * NN + cc) = __halves2half2(h0, h1);
                    *(__half2*)(CL + (size_t)rr * NN + cc) = __halves2half2(l0, l1);
                }
            }
        }
    }
}

// ---------------------------------------------------------------------------
// gemm1 body: C fp32 = A @ B^T, single fp16 product. BK=64. (R16, unchanged)
// ---------------------------------------------------------------------------
template <int NN, int KK>
__device__ __forceinline__ void gemm1_run(
    char* smem,
    const __half* __restrict__ A, const __half* __restrict__ B,
    float* __restrict__ C)
{
    const int tid  = threadIdx.x;
    const int wid  = tid >> 5;
    const int lane = tid & 31;
    const int wm   = wid >> 1;
    const int wn   = wid & 1;
    const int m0   = blockIdx.y * 128;
    const int n0   = blockIdx.x * 128;

    uint32_t sbase = (uint32_t)__cvta_generic_to_shared(smem);
    const uint32_t ST0 = (sbase + 1023) & ~1023u;

    constexpr int T = KK >> 6;

    const int fc  = tid & 7;
    const int fr0 = tid >> 3;
    const int kg0 = fc * 8;

    const __half* pA[4];
    const __half* pB[4];
    uint32_t so[4];
#pragma unroll
    for (int i = 0; i < 4; i++) {
        int row = fr0 + i * 32;
        pA[i] = A + (size_t)(m0 + row) * KK + kg0;
        pB[i] = B + (size_t)(n0 + row) * KK + kg0;
        so[i] = (uint32_t)row * 128 + (uint32_t)(fc ^ (row & 7)) * 16;
    }

    auto fill = [&](int s) {
        const uint32_t sa = ST0 + s * STAGE;
#pragma unroll
        for (int i = 0; i < 4; i++) {
            cp16(sa + so[i],          pA[i]);
            cp16(sa + so[i] + 16384u, pB[i]);
            pA[i] += 64;
            pB[i] += 64;
        }
        cp_commit();
    };

    const uint32_t c0 = lane >> 4;
    uint32_t offA[2], offB[4];
#pragma unroll
    for (int mt = 0; mt < 2; mt++) {
        int mr = wm * 32 + mt * 16 + (lane & 15);
        offA[mt] = (uint32_t)mr * 128 + ((c0 ^ (uint32_t)(mr & 7)) * 16);
    }
#pragma unroll
    for (int ng = 0; ng < 4; ng++) {
        int nr = wn * 64 + ng * 16 + (lane & 15);
        offB[ng] = 16384u + (uint32_t)nr * 128 + ((c0 ^ (uint32_t)(nr & 7)) * 16);
    }

    float acc[2][8][4];
#pragma unroll
    for (int mt = 0; mt < 2; mt++)
#pragma unroll
        for (int nt = 0; nt < 8; nt++)
#pragma unroll
            for (int j = 0; j < 4; j++) acc[mt][nt][j] = 0.0f;

    fill(0); fill(1);

    int scur = 0, snext2 = 2;
    for (int kt = 0; kt < T; kt++) {
        cp_wait1();
        __syncthreads();
        if (kt + 2 < T) fill(snext2); else cp_commit();

        const uint32_t sa = ST0 + scur * STAGE;
        scur = (scur == 2) ? 0 : scur + 1;
        snext2 = (snext2 == 2) ? 0 : snext2 + 1;

#pragma unroll
        for (int ks = 0; ks < 4; ks++) {
            const uint32_t kx = (uint32_t)ks << 5;
            uint32_t a[2][4];
#pragma unroll
            for (int mt = 0; mt < 2; mt++)
                ldmx4(a[mt], (sa + offA[mt]) ^ kx);
#pragma unroll
            for (int ng = 0; ng < 4; ng++) {
                uint32_t bb[4];
                ldmx4(bb, (sa + offB[ng]) ^ kx);
#pragma unroll
                for (int mt = 0; mt < 2; mt++)
#pragma unroll
                    for (int o = 0; o < 2; o++)
                        mma16816h(acc[mt][2 * ng + o], a[mt], bb[o], bb[2 + o]);
            }
        }
    }

    const int gm0 = m0 + wm * 32;
    const int gn0 = n0 + wn * 64;
#pragma unroll
    for (int mt = 0; mt < 2; mt++) {
#pragma unroll
        for (int nt = 0; nt < 8; nt++) {
            int r  = gm0 + mt * 16 + (lane >> 2);
            int cc = gn0 + nt * 8 + 2 * (lane & 3);
            *(float2*)(C + (size_t)r * NN + cc) =
                make_float2(acc[mt][nt][0], acc[mt][nt][1]);
            *(float2*)(C + (size_t)(r + 8) * NN + cc) =
                make_float2(acc[mt][nt][2], acc[mt][nt][3]);
        }
    }
}

// ---------------------------------------------------------------------------
// batched-direction GEMM kernels (operands from device globals, z selects dir)
// ---------------------------------------------------------------------------
__global__ __launch_bounds__(256, 2) void proj_both()
{
    extern __shared__ char smem[];
    const int z = blockIdx.z;
    const size_t bo = (size_t)(z & 7) * (SEQ * HDIM);
    if (z < 8)
        gemm3_run<1, HDIM, HDIM>(smem, g_s2h + bo, g_s2l + bo, g_w1h, g_w1l,
                                 nullptr, g_sh1h + bo, g_sh1l + bo);
    else
        gemm3_run<1, HDIM, HDIM>(smem, g_s1h + bo, g_s1l + bo, g_w2h, g_w2l,
                                 nullptr, g_sh2h + bo, g_sh2l + bo);
}

__global__ __launch_bounds__(256, 2) void score_both()
{
    extern __shared__ char smem[];
    const int z = blockIdx.z;
    const size_t bo = (size_t)(z & 7) * (SEQ * HDIM);
    const size_t co = (size_t)(z & 7) * (SEQ * SEQ) + (z < 8 ? 0 : ES);
    if (z < 8)
        gemm3_run<0, SEQ, HDIM>(smem, g_s1h + bo, g_s1l + bo,
                                g_sh1h + bo, g_sh1l + bo,
                                g_sc + co, nullptr, nullptr);
    else
        gemm3_run<0, SEQ, HDIM>(smem, g_s2h + bo, g_s2l + bo,
                                g_sh2h + bo, g_sh2l + bo,
                                g_sc + co, nullptr, nullptr);
}

__global__ __launch_bounds__(256, 2) void pv_both(float* __restrict__ out)
{
    extern __shared__ char smem[];
    const int z = blockIdx.z;
    const size_t ao = (size_t)(z & 7) * (SEQ * SEQ) + (z < 8 ? 0 : ES);
    const size_t bo = (size_t)(z & 7) * (SEQ * HDIM);
    float* C = out + (z < 8 ? 0 : E1) + bo;
    if (z < 8)
        gemm1_run<HDIM, SEQ>(smem, g_at + ao, g_s2t + bo, C);
    else
        gemm1_run<HDIM, SEQ>(smem, g_at + ao, g_s1t + bo, C);
}

// ---------------------------------------------------------------------------
// prep_S: read S once; emit fp16 hi/lo (row-major) and fp16 transposed.
// grid (HDIM/32, SEQ/32, BATCH), block (32, 8).
// ---------------------------------------------------------------------------
__global__ __launch_bounds__(256) void prep_S(
    const float* __restrict__ S, __half* __restrict__ hi,
    __half* __restrict__ lo, __half* __restrict__ Tt)
{
    __shared__ float t[32][33];
    const int b  = blockIdx.z;
    const int h0 = blockIdx.x * 32;
    const int n0 = blockIdx.y * 32;
    const int tx = threadIdx.x, ty = threadIdx.y;
    const size_t ibase = (size_t)b * SEQ * HDIM;
#pragma unroll
    for (int i = 0; i < 4; i++) {
        int r = ty + i * 8;
        float v = S[ibase + (size_t)(n0 + r) * HDIM + h0 + tx];
        t[r][tx] = v;
        __half h, l;
        hsplit(v, h, l);
        size_t o = ibase + (size_t)(n0 + r) * HDIM + h0 + tx;
        hi[o] = h;
        lo[o] = l;
    }
    __syncthreads();
    const size_t obase = (size_t)b * HDIM * SEQ;
#pragma unroll
    for (int i = 0; i < 4; i++) {
        int r = ty + i * 8;
        Tt[obase + (size_t)(h0 + r) * SEQ + n0 + tx] = __float2half_rn(t[tx][r]);
    }
}

// ---------------------------------------------------------------------------
// split both W's in one launch: blocks [0,512) -> W1, [512,1024) -> W2
// ---------------------------------------------------------------------------
__global__ __launch_bounds__(256) void split_W_both(
    const float* __restrict__ W1, const float* __restrict__ W2)
{
    const bool second = blockIdx.x >= 512;
    const float* x = second ? W2 : W1;
    __half* hi = second ? g_w2h : g_w1h;
    __half* lo = second ? g_w2l : g_w1l;
    const size_t n4 = EW / 4;
    size_t i = (size_t)(blockIdx.x & 511) * blockDim.x + threadIdx.x;
    size_t stride = (size_t)512 * blockDim.x;
    for (; i < n4; i += stride) {
        float4 v = ((const float4*)x)[i];
        __half h0, l0, h1, l1, h2, l2, h3, l3;
        hsplit(v.x, h0, l0); hsplit(v.y, h1, l1);
        hsplit(v.z, h2, l2); hsplit(v.w, h3, l3);
        ((__half2*)hi)[2 * i]     = __halves2half2(h0, h1);
        ((__half2*)hi)[2 * i + 1] = __halves2half2(h2, h3);
        ((__half2*)lo)[2 * i]     = __halves2half2(l0, l1);
        ((__half2*)lo)[2 * i + 1] = __halves2half2(l2, l3);
    }
}

// ---------------------------------------------------------------------------
// softmax rows (len 2048) -> fp16; one launch covers both directions
// (g_sc / g_at are 2*ES; blockIdx.x in [0, 2*BATCH*SEQ)).
// ---------------------------------------------------------------------------
__global__ __launch_bounds__(256) void softmax_both()
{
    const float* row = g_sc + (size_t)blockIdx.x * SEQ;
    const int tid = threadIdx.x;
    const int lane = tid & 31, wrp = tid >> 5;
    __shared__ float red[8];

    float v[8];
    float4 v0 = *(const float4*)(row + tid * 8);
    float4 v1 = *(const float4*)(row + tid * 8 + 4);
    v[0]=v0.x; v[1]=v0.y; v[2]=v0.z; v[3]=v0.w;
    v[4]=v1.x; v[5]=v1.y; v[6]=v1.z; v[7]=v1.w;

    float m = v[0];
#pragma unroll
    for (int i = 1; i < 8; i++) m = fmaxf(m, v[i]);
#pragma unroll
    for (int o = 16; o > 0; o >>= 1) m = fmaxf(m, __shfl_xor_sync(~0u, m, o));
    if (lane == 0) red[wrp] = m;
    __syncthreads();
    m = red[0];
#pragma unroll
    for (int w = 1; w < 8; w++) m = fmaxf(m, red[w]);
    __syncthreads();

    float s = 0.0f;
#pragma unroll
    for (int i = 0; i < 8; i++) { v[i] = __expf(v[i] - m); s += v[i]; }
#pragma unroll
    for (int o = 16; o > 0; o >>= 1) s += __shfl_xor_sync(~0u, s, o);
    if (lane == 0) red[wrp] = s;
    __syncthreads();
    s = red[0];
#pragma unroll
    for (int w = 1; w < 8; w++) s += red[w];
    float inv = 1.0f / s;

    __half2* ph = (__half2*)(g_at + (size_t)blockIdx.x * SEQ + tid * 8);
#pragma unroll
    for (int i = 0; i < 4; i++)
        ph[i] = __floats2half2_rn(v[2 * i] * inv, v[2 * i + 1] * inv);
}

// ---------------------------------------------------------------------------
// launch: 7 kernels. Index 3 (ncu-captured) = proj_both.
// deps: proj(3) <- prep_S(0,1), split_W(2); score(4) <- proj + prep;
//       softmax(5) <- score; pv(6) <- softmax + prep (transposed).
// ---------------------------------------------------------------------------
extern "C" void kernel_launch(void* const* d_in, const int* in_sizes, int n_in,
                              void* d_out, int out_size)
{
    const float* S1 = (const float*)d_in[0];
    const float* S2 = (const float*)d_in[1];
    const float* W1 = (const float*)d_in[2];
    const float* W2 = (const float*)d_in[3];

    float* out = (float*)d_out;

    __half *s1h, *s1l, *s2h, *s2l, *s1t, *s2t;
    cudaGetSymbolAddress((void**)&s1h, g_s1h);
    cudaGetSymbolAddress((void**)&s1l, g_s1l);
    cudaGetSymbolAddress((void**)&s2h, g_s2h);
    cudaGetSymbolAddress((void**)&s2l, g_s2l);
    cudaGetSymbolAddress((void**)&s1t, g_s1t);
    cudaGetSymbolAddress((void**)&s2t, g_s2t);

    cudaFuncSetAttribute(proj_both,  cudaFuncAttributeMaxDynamicSharedMemorySize, SMEM_REQ);
    cudaFuncSetAttribute(score_both, cudaFuncAttributeMaxDynamicSharedMemorySize, SMEM_REQ);
    cudaFuncSetAttribute(pv_both,    cudaFuncAttributeMaxDynamicSharedMemorySize, SMEM_REQ);

    dim3 blk(256);
    dim3 tb(32, 8);
    dim3 tg(HDIM / 32, SEQ / 32, BATCH);

    dim3 gProj(HDIM / 128, SEQ / 128, 2 * BATCH);   // 8 x 16 x 16
    dim3 gScore(SEQ / 128, SEQ / 128, 2 * BATCH);   // 16 x 16 x 16
    dim3 gPV(HDIM / 128, SEQ / 128, 2 * BATCH);     // 8 x 16 x 16

    prep_S<<<tg, tb>>>(S1, s1h, s1l, s1t);                 // 0
    prep_S<<<tg, tb>>>(S2, s2h, s2l, s2t);                 // 1
    split_W_both<<<1024, 256>>>(W1, W2);                   // 2
    proj_both<<<gProj, blk, SMEM_REQ>>>();                 // 3 (ncu)
    score_both<<<gScore, blk, SMEM_REQ>>>();               // 4
    softmax_both<<<2 * BATCH * SEQ, 256>>>();              // 5
    pv_both<<<gPV, blk, SMEM_REQ>>>(out);                  // 6
}